// round 15
// baseline (speedup 1.0000x reference)
#include <cuda_runtime.h>

#define NN 50000
#define EE 800000
#define ET 850000   // EE + NN self-loops
#define SB 512      // scan block size
#define NB ((NN + SB - 1) / SB)   // 98 scan blocks

// ---------------- scratch (device globals; no runtime allocation) ----------
__device__ int   g_deg[NN];
__device__ int   g_cur[NN];
__device__ int   g_off[NN + 1];
__device__ float g_dis[NN];
__device__ int   g_part[NB];
__device__ int2  g_srcw[ET];            // (src index, weight bits) packed
__device__ float g_s[NN];               // A·1
__device__ float g_s2[NN];              // A²·1
__device__ float g_C[96 * 32];          // W2·W3·W4
__device__ float g_v2[32];              // b2·W3·W4
__device__ float g_v3[32];              // b3·W4
__device__ float g_bufA[(size_t)NN * 128];
__device__ float g_bufB[(size_t)NN * 128];

// Compile-time buffer selector (no host-side symbol lookup).
enum Which { A_, B_, X_ };
template <Which W>
__device__ __forceinline__ const float* inbuf(const float* ext) {
    if constexpr (W == A_) return g_bufA;
    else if constexpr (W == B_) return g_bufB;
    else return ext;
}
template <Which W>
__device__ __forceinline__ float* outbuf(float* ext) {
    if constexpr (W == A_) return g_bufA;
    else if constexpr (W == B_) return g_bufB;
    else return ext;
}

// ---------------- graph prep ------------------------------------------------
// edge_index is int32 (JAX x64 disabled). Count-only pass.
__global__ void k_count(const int* __restrict__ ei) {
    int e = blockIdx.x * blockDim.x + threadIdx.x;
    if (e >= EE) return;
    int c = ei[EE + e];
    if ((unsigned)c >= NN) c = 0;   // never trap on bad data
    atomicAdd(&g_deg[c], 1);
}

// per-block sums of (deg[i]+1)
__global__ __launch_bounds__(SB) void k_scan1() {
    __shared__ int s[SB];
    int t = threadIdx.x;
    int i = blockIdx.x * SB + t;
    s[t] = (i < NN) ? (g_deg[i] + 1) : 0;
    __syncthreads();
#pragma unroll
    for (int o = SB / 2; o > 0; o >>= 1) {
        if (t < o) s[t] += s[t + o];
        __syncthreads();
    }
    if (t == 0) g_part[blockIdx.x] = s[0];
}

// scan of partials (redundant per block) + local scan + write g_off, g_dis
__global__ __launch_bounds__(SB) void k_scan3() {
    __shared__ int ps[128];
    __shared__ int s[SB];
    int t = threadIdx.x;
    if (t < 128) ps[t] = (t < NB) ? g_part[t] : 0;
    __syncthreads();
#pragma unroll
    for (int o = 1; o < 128; o <<= 1) {
        int u = 0;
        if (t < 128 && t >= o) u = ps[t - o];
        __syncthreads();
        if (t < 128) ps[t] += u;
        __syncthreads();
    }
    int base = ps[blockIdx.x] - g_part[blockIdx.x];   // exclusive prefix
    if (blockIdx.x == 0 && t == 0) g_off[NN] = ET;

    int i = blockIdx.x * SB + t;
    int d = (i < NN) ? g_deg[i] : 0;
    int v = (i < NN) ? (d + 1) : 0;
    s[t] = v;
    __syncthreads();
#pragma unroll
    for (int o = 1; o < SB; o <<= 1) {
        int u = (t >= o) ? s[t - o] : 0;
        __syncthreads();
        s[t] += u;
        __syncthreads();
    }
    if (i < NN) {
        g_off[i] = base + s[t] - v;
        g_dis[i] = rsqrtf((float)(d + 1));
    }
}

// fill CSR: edges (read ei directly) + self loops; one packed 8B store/edge
__global__ void k_fillself(const int* __restrict__ ei) {
    int e = blockIdx.x * blockDim.x + threadIdx.x;
    if (e < EE) {
        int r = ei[e];
        int c = ei[EE + e];
        if ((unsigned)r >= NN) r = 0;
        if ((unsigned)c >= NN) c = 0;
        int p = atomicAdd(&g_cur[c], 1);
        float w = g_dis[r] * g_dis[c];
        g_srcw[g_off[c] + p] = make_int2(r, __float_as_int(w));
    } else if (e < EE + NN) {
        int n = e - EE;
        float d = g_dis[n];
        g_srcw[g_off[n + 1] - 1] = make_int2(n, __float_as_int(d * d));
    }
}

// ---------------- weight precompute: C=W2(W3W4), v2=b2(W3W4), v3=b3W4 ------
__global__ __launch_bounds__(512) void k_wprep(const float* __restrict__ W2,
                                               const float* __restrict__ W3,
                                               const float* __restrict__ W4,
                                               const float* __restrict__ b2,
                                               const float* __restrict__ b3) {
    __shared__ float Ts[128 * 32];   // W3·W4
    int t = threadIdx.x;
    for (int i = t; i < 128 * 32; i += 512) {
        int k = i >> 5, o = i & 31;
        float sum = 0.f;
        for (int j = 0; j < 64; j++) sum += W3[k * 64 + j] * W4[j * 32 + o];
        Ts[i] = sum;
    }
    if (t < 32) {
        float sum = 0.f;
        for (int j = 0; j < 64; j++) sum += b3[j] * W4[j * 32 + t];
        g_v3[t] = sum;
    }
    __syncthreads();
    for (int i = t; i < 96 * 32; i += 512) {
        int k = i >> 5, o = i & 31;
        float sum = 0.f;
        for (int j = 0; j < 128; j++) sum += W2[k * 128 + j] * Ts[j * 32 + o];
        g_C[i] = sum;
    }
    if (t < 32) {
        float sum = 0.f;
        for (int j = 0; j < 128; j++) sum += b2[j] * Ts[j * 32 + t];
        g_v2[t] = sum;
    }
}

// ---------------- scalar aggregation (F=29) + replay cleanup ----------------
template <int F, bool BIAS, bool CLEAN, Which SRC, Which DST>
__global__ __launch_bounds__(256) void k_agg(const float* __restrict__ ext_in,
                                             const float* __restrict__ b,
                                             float* __restrict__ ext_out) {
    const float* __restrict__ h = inbuf<SRC>(ext_in);
    float* __restrict__ out = outbuf<DST>(ext_out);
    constexpr int NACC = (F + 31) / 32;
    int warp = (blockIdx.x * blockDim.x + threadIdx.x) >> 5;
    int lane = threadIdx.x & 31;
    if (warp >= NN) return;
    int n = warp;
    if (CLEAN && lane == 0) { g_deg[n] = 0; g_cur[n] = 0; }  // for next replay
    int s = g_off[n], e = g_off[n + 1];
    float acc[NACC];
#pragma unroll
    for (int j = 0; j < NACC; j++) acc[j] = 0.f;
    for (int i = s; i < e; i++) {
        int2 sw = g_srcw[i];
        int src = sw.x;
        float w = __int_as_float(sw.y);
        const float* hp = h + (size_t)src * F;
#pragma unroll
        for (int j = 0; j < NACC; j++) {
            int f = lane + 32 * j;
            if (f < F) acc[j] += w * __ldg(hp + f);
        }
    }
    float* op = out + (size_t)n * F;
#pragma unroll
    for (int j = 0; j < NACC; j++) {
        int f = lane + 32 * j;
        if (f < F) op[f] = acc[j] + (BIAS ? b[f] : 0.f);
    }
}

// ---------------- 32-wide aggregation passes of the collapsed layers --------
// MODE 1: t = A·u,  also s  = A·1   (Σw per node)
// MODE 2: t = A·t1, also s2 = A·s   (Σ w·s[src])
// MODE 3: t = A·t2, epilogue out = t + s2·v2 + s·v3 + b4
template <int MODE, Which SRC, Which DST>
__global__ __launch_bounds__(256) void k_agg32(const float* __restrict__ ext_in,
                                               const float* __restrict__ b4,
                                               float* __restrict__ ext_out) {
    const float* __restrict__ h = inbuf<SRC>(ext_in);
    float* __restrict__ out = outbuf<DST>(ext_out);
    int warp = (blockIdx.x * blockDim.x + threadIdx.x) >> 5;
    int lane = threadIdx.x & 31;
    if (warp >= NN) return;
    int g = lane >> 3;       // 4 edge-groups of 8 lanes
    int q = lane & 7;        // float4 index within the 32-float row
    int s0 = g_off[warp], e0 = g_off[warp + 1];
    float4 acc = make_float4(0.f, 0.f, 0.f, 0.f);
    float ws = 0.f;
    for (int i = s0 + g; i < e0; i += 4) {
        int2 sw = g_srcw[i];
        float w = __int_as_float(sw.y);
        float4 v = __ldg((const float4*)(h + (size_t)sw.x * 32) + q);
        acc.x += w * v.x; acc.y += w * v.y;
        acc.z += w * v.z; acc.w += w * v.w;
        if constexpr (MODE == 1) ws += w;
        if constexpr (MODE == 2) ws += w * __ldg(&g_s[sw.x]);
    }
#pragma unroll
    for (int off = 8; off <= 16; off <<= 1) {
        acc.x += __shfl_xor_sync(0xffffffffu, acc.x, off);
        acc.y += __shfl_xor_sync(0xffffffffu, acc.y, off);
        acc.z += __shfl_xor_sync(0xffffffffu, acc.z, off);
        acc.w += __shfl_xor_sync(0xffffffffu, acc.w, off);
        if constexpr (MODE == 1 || MODE == 2)
            ws += __shfl_xor_sync(0xffffffffu, ws, off);
    }
    if constexpr (MODE == 1) { if (lane == 0) g_s[warp] = ws; }
    if constexpr (MODE == 2) { if (lane == 0) g_s2[warp] = ws; }
    if (g == 0) {
        if constexpr (MODE == 3) {
            float ss = g_s[warp], ss2 = g_s2[warp];
            float4 v2q = *(const float4*)&g_v2[q * 4];
            float4 v3q = *(const float4*)&g_v3[q * 4];
            float4 b4q = __ldg((const float4*)b4 + q);
            acc.x += ss2 * v2q.x + ss * v3q.x + b4q.x;
            acc.y += ss2 * v2q.y + ss * v3q.y + b4q.y;
            acc.z += ss2 * v2q.z + ss * v3q.z + b4q.z;
            acc.w += ss2 * v2q.w + ss * v3q.w + b4q.w;
        }
        ((float4*)(out + (size_t)warp * 32))[q] = acc;
    }
}

// ---------------- fused GEMM: u = relu(aggx·W1 + b1)·C ----------------------
// 64-node tile per 256-thread block. h1 (64x96) lives only in shared memory.
// Phase-1 staging (Xs, W1s) overlaid with phase-2 Cs via union. Weight inner
// loads scalar (R10 lesson).
template <Which SRC, Which DST>
__global__ __launch_bounds__(256) void k_gemm_fused(const float* __restrict__ ext_in,
                                                    const float* __restrict__ W1,
                                                    const float* __restrict__ b1,
                                                    float* __restrict__ ext_out) {
    const float* __restrict__ x = inbuf<SRC>(ext_in);   // 29-wide rows
    float* __restrict__ out = outbuf<DST>(ext_out);     // 32-wide rows

    __shared__ float H[64][97];                         // relu(h1), padded
    __shared__ union U {
        struct { float Xs[32][64]; float W1s[32][96]; } p1;  // 20 KB
        float Cs[96][32];                                    // 12 KB
    } u;

    int t  = threadIdx.x;
    int tx = t & 15, ty = t >> 4;        // 16 x 16
    int mB = blockIdx.x * 64;

    // stage Xs (k-major), zero-pad k>=29 and nodes >= NN
    {
        int node = t & 63;
        int k0 = (t >> 6) * 8;
        bool mv = (mB + node) < NN;
        const float* xr = x + (size_t)(mB + node) * 29;
#pragma unroll
        for (int j = 0; j < 8; j++) {
            int k = k0 + j;
            u.p1.Xs[k][node] = (mv && k < 29) ? xr[k] : 0.f;
        }
    }
    // stage W1s (32x96), zero-pad k>=29
    for (int i = t; i < 32 * 96; i += 256) {
        int k = i / 96, o = i % 96;
        u.p1.W1s[k][o] = (k < 29) ? W1[i - 3 * 96] * 0.f + W1[k * 96 + o] : 0.f;
    }
    __syncthreads();

    // phase 1: H = relu(Xs^T · W1 + b1)  (64 x 96)
    {
        float acc[4][6];
#pragma unroll
        for (int i = 0; i < 4; i++)
#pragma unroll
            for (int j = 0; j < 6; j++) acc[i][j] = 0.f;
#pragma unroll
        for (int kk = 0; kk < 32; kk++) {
            float4 xa = *(const float4*)&u.p1.Xs[kk][ty * 4];
            float wv[6];
#pragma unroll
            for (int j = 0; j < 6; j++) wv[j] = u.p1.W1s[kk][tx * 6 + j];
#pragma unroll
            for (int j = 0; j < 6; j++) {
                acc[0][j] += xa.x * wv[j];
                acc[1][j] += xa.y * wv[j];
                acc[2][j] += xa.z * wv[j];
                acc[3][j] += xa.w * wv[j];
            }
        }
#pragma unroll
        for (int i = 0; i < 4; i++)
#pragma unroll
            for (int j = 0; j < 6; j++) {
                float v = acc[i][j] + __ldg(&b1[tx * 6 + j]);
                H[ty * 4 + i][tx * 6 + j] = fmaxf(v, 0.f);
            }
    }
    __syncthreads();
    // load C (96x32) over the staging union
    for (int i = t; i < 96 * 32; i += 256) ((float*)u.Cs)[i] = g_C[i];
    __syncthreads();

    // phase 2: out = H · C  (64 x 32)
    {
        float a2[4][2] = {{0.f, 0.f}, {0.f, 0.f}, {0.f, 0.f}, {0.f, 0.f}};
#pragma unroll 4
        for (int kk = 0; kk < 96; kk++) {
            float h0 = H[ty * 4 + 0][kk];
            float h1 = H[ty * 4 + 1][kk];
            float h2 = H[ty * 4 + 2][kk];
            float h3 = H[ty * 4 + 3][kk];
            float w0 = u.Cs[kk][tx * 2 + 0];
            float w1 = u.Cs[kk][tx * 2 + 1];
            a2[0][0] += h0 * w0; a2[0][1] += h0 * w1;
            a2[1][0] += h1 * w0; a2[1][1] += h1 * w1;
            a2[2][0] += h2 * w0; a2[2][1] += h2 * w1;
            a2[3][0] += h3 * w0; a2[3][1] += h3 * w1;
        }
#pragma unroll
        for (int i = 0; i < 4; i++) {
            int m = mB + ty * 4 + i;
            if (m < NN) {
                out[(size_t)m * 32 + tx * 2 + 0] = a2[i][0];
                out[(size_t)m * 32 + tx * 2 + 1] = a2[i][1];
            }
        }
    }
}

// ---------------- launch ----------------------------------------------------
static inline int ceil_div(int a, int b) { return (a + b - 1) / b; }

extern "C" void kernel_launch(void* const* d_in, const int* in_sizes, int n_in,
                              void* d_out, int out_size) {
    const float* x  = (const float*)d_in[0];
    const int*   ei = (const int*)d_in[1];   // int32 edge_index (2, E)
    const float* W1 = (const float*)d_in[2]; const float* b1 = (const float*)d_in[3];
    const float* W2 = (const float*)d_in[4]; const float* b2 = (const float*)d_in[5];
    const float* W3 = (const float*)d_in[6]; const float* b3 = (const float*)d_in[7];
    const float* W4 = (const float*)d_in[8]; const float* b4 = (const float*)d_in[9];
    float* out = (float*)d_out;

    const int TB = 256;
    const int gE  = ceil_div(EE, TB);
    const int gET = ceil_div(ET, TB);
    const int gW  = ceil_div(NN, TB / 32);   // one warp per node
    const int gF  = ceil_div(NN, 64);        // fused-gemm node-blocks (782)

    // weight precompute (one block) + graph prep
    k_wprep<<<1, 512>>>(W2, W3, W4, b2, b3);
    k_count<<<gE, TB>>>(ei);
    k_scan1<<<NB, SB>>>();
    k_scan3<<<NB, SB>>>();
    k_fillself<<<gET, TB>>>(ei);

    // layer 1 aggregate (29-wide), then fused relu-GEMM chain to 32-wide u
    k_agg<29, false, true, X_, A_><<<gW, TB>>>(x, nullptr, nullptr);
    k_gemm_fused<A_, B_><<<gF, TB>>>(nullptr, W1, b1, nullptr);

    // collapsed layers 2-4: t = A u (+s) ; t = A t (+s2) ; out = A t + eps
    k_agg32<1, B_, A_><<<gW, TB>>>(nullptr, nullptr, nullptr);
    k_agg32<2, A_, B_><<<gW, TB>>>(nullptr, nullptr, nullptr);
    k_agg32<3, B_, X_><<<gW, TB>>>(nullptr, b4, out);

    (void)in_sizes; (void)n_in; (void)out_size;
}